// round 1
// baseline (speedup 1.0000x reference)
#include <cuda_runtime.h>
#include <math.h>

#define FDIM 128
#define HEADS 4
#define CH 32
#define NMAX 50000
#define EMAX 1600000
#define EPMAX (EMAX + NMAX)

// ---- scratch (static device globals; allocation-free) ----
__device__ float    g_h [NMAX * FDIM];     // per-layer transformed features
__device__ float    g_xa[NMAX * FDIM];     // ping buffer
__device__ float    g_xb[NMAX * FDIM];     // pong buffer
__device__ float    g_e [(size_t)EPMAX * HEADS]; // per-edge e / ex
__device__ float    g_as[NMAX * HEADS];
__device__ float    g_ad[NMAX * HEADS];
__device__ unsigned g_m [NMAX * HEADS];    // encoded segment max
__device__ float    g_s [NMAX * HEADS];    // segment sum

// order-preserving float<->uint encoding (monotone; uint 0 == minimum)
__device__ __forceinline__ unsigned enc_f(float f) {
    unsigned u = __float_as_uint(f);
    return (u & 0x80000000u) ? ~u : (u | 0x80000000u);
}
__device__ __forceinline__ float dec_f(unsigned k) {
    return (k & 0x80000000u) ? __uint_as_float(k ^ 0x80000000u)
                             : __uint_as_float(~k);
}

// ---------------- GEMM: C[N,128] = A[N,128] @ B[128,128] ----------------
#define BM 64
#define BK 16
__global__ void gemm_kernel(const float* __restrict__ A,
                            const float* __restrict__ B,
                            float* __restrict__ C, int N) {
    __shared__ float As[BM][BK];
    __shared__ float Bs[BK][FDIM];
    int tid = threadIdx.x;             // 256 threads
    int tx = tid & 31;                 // col group (4 cols each)
    int ty = tid >> 5;                 // row group (8 rows each)
    int rowBlock = blockIdx.x * BM;

    float acc[8][4];
    #pragma unroll
    for (int i = 0; i < 8; i++)
        #pragma unroll
        for (int j = 0; j < 4; j++) acc[i][j] = 0.f;

    int arow = tid >> 2;               // 0..63
    int acol = (tid & 3) * 4;          // 0,4,8,12
    int brow = tid >> 5;               // 0..7
    int bcol = (tid & 31) * 4;

    for (int k0 = 0; k0 < FDIM; k0 += BK) {
        int gr = rowBlock + arow;
        float4 av = make_float4(0.f, 0.f, 0.f, 0.f);
        if (gr < N) av = *(const float4*)&A[(size_t)gr * FDIM + k0 + acol];
        *(float4*)&As[arow][acol] = av;
        *(float4*)&Bs[brow][bcol]     = *(const float4*)&B[(size_t)(k0 + brow) * FDIM + bcol];
        *(float4*)&Bs[brow + 8][bcol] = *(const float4*)&B[(size_t)(k0 + brow + 8) * FDIM + bcol];
        __syncthreads();
        #pragma unroll
        for (int kk = 0; kk < BK; kk++) {
            float a[8];
            #pragma unroll
            for (int i = 0; i < 8; i++) a[i] = As[ty * 8 + i][kk];
            float4 b4 = *(float4*)&Bs[kk][tx * 4];
            #pragma unroll
            for (int i = 0; i < 8; i++) {
                acc[i][0] += a[i] * b4.x;
                acc[i][1] += a[i] * b4.y;
                acc[i][2] += a[i] * b4.z;
                acc[i][3] += a[i] * b4.w;
            }
        }
        __syncthreads();
    }
    #pragma unroll
    for (int i = 0; i < 8; i++) {
        int gr = rowBlock + ty * 8 + i;
        if (gr < N) {
            float4 ov = make_float4(acc[i][0], acc[i][1], acc[i][2], acc[i][3]);
            *(float4*)&C[(size_t)gr * FDIM + tx * 4] = ov;
        }
    }
}

// ---------------- per-node prep: alpha_s/alpha_d, init m/s/out ----------------
__global__ void prep_kernel(const float* __restrict__ h,
                            const float* __restrict__ att_s,
                            const float* __restrict__ att_d,
                            const float* __restrict__ bias,
                            float* __restrict__ out,
                            float* __restrict__ as_, float* __restrict__ ad_,
                            unsigned* __restrict__ m, float* __restrict__ s,
                            int N) {
    int n = blockIdx.x;
    if (n >= N) return;
    int c = threadIdx.x;              // 0..127
    int head = c >> 5, lane = c & 31;
    float hv = h[(size_t)n * FDIM + c];
    float vs = hv * att_s[head * CH + lane];
    float vd = hv * att_d[head * CH + lane];
    #pragma unroll
    for (int off = 16; off; off >>= 1) {
        vs += __shfl_down_sync(0xffffffffu, vs, off);
        vd += __shfl_down_sync(0xffffffffu, vd, off);
    }
    if (lane == 0) {
        as_[n * HEADS + head] = vs;
        ad_[n * HEADS + head] = vd;
    }
    out[(size_t)n * FDIM + c] = bias[c];
    if (c < HEADS) m[n * HEADS + c] = 0u;
    else if (c < 2 * HEADS) s[n * HEADS + (c - HEADS)] = 0.f;
}

// ---------------- edge pass 1: e = leaky_relu(as[src]+ad[dst]); segment max ----------------
__global__ void edge_max_kernel(const int* __restrict__ ei,
                                const float* __restrict__ as_,
                                const float* __restrict__ ad_,
                                float* __restrict__ e_out,
                                unsigned* __restrict__ m,
                                int E, int EP) {
    int eid = blockIdx.x * blockDim.x + threadIdx.x;
    if (eid >= EP) return;
    int src, dst;
    if (eid < E) { src = ei[eid]; dst = ei[E + eid]; }
    else         { src = dst = eid - E; }
    float4 a = *(const float4*)&as_[src * HEADS];
    float4 b = *(const float4*)&ad_[dst * HEADS];
    float ev[4] = {a.x + b.x, a.y + b.y, a.z + b.z, a.w + b.w};
    #pragma unroll
    for (int hh = 0; hh < 4; hh++) {
        float e = ev[hh];
        e = (e > 0.f) ? e : 0.2f * e;
        ev[hh] = e;
        atomicMax(&m[dst * HEADS + hh], enc_f(e));
    }
    *(float4*)&e_out[(size_t)eid * HEADS] = make_float4(ev[0], ev[1], ev[2], ev[3]);
}

// ---------------- edge pass 2: ex = exp(e - m[dst]); segment sum ----------------
__global__ void edge_sum_kernel(const int* __restrict__ ei,
                                float* __restrict__ e_io,
                                const unsigned* __restrict__ m,
                                float* __restrict__ s,
                                int E, int EP) {
    int eid = blockIdx.x * blockDim.x + threadIdx.x;
    if (eid >= EP) return;
    int dst = (eid < E) ? ei[E + eid] : (eid - E);
    float4 e4 = *(const float4*)&e_io[(size_t)eid * HEADS];
    uint4 mu = *(const uint4*)&m[dst * HEADS];
    float ex0 = __expf(e4.x - dec_f(mu.x));
    float ex1 = __expf(e4.y - dec_f(mu.y));
    float ex2 = __expf(e4.z - dec_f(mu.z));
    float ex3 = __expf(e4.w - dec_f(mu.w));
    *(float4*)&e_io[(size_t)eid * HEADS] = make_float4(ex0, ex1, ex2, ex3);
    atomicAdd(&s[dst * HEADS + 0], ex0);
    atomicAdd(&s[dst * HEADS + 1], ex1);
    atomicAdd(&s[dst * HEADS + 2], ex2);
    atomicAdd(&s[dst * HEADS + 3], ex3);
}

// ---------------- edge pass 3: out[dst] += h[src] * a  (warp per edge) ----------------
__global__ void edge_aggr_kernel(const int* __restrict__ ei,
                                 const float* __restrict__ ex,
                                 const float* __restrict__ s,
                                 const float* __restrict__ h,
                                 float* __restrict__ out,
                                 int E, int EP) {
    int gtid = blockIdx.x * blockDim.x + threadIdx.x;
    int eid = gtid >> 5;
    int lane = gtid & 31;
    if (eid >= EP) return;
    int src, dst;
    if (eid < E) { src = ei[eid]; dst = ei[E + eid]; }
    else         { src = dst = eid - E; }
    int head = lane >> 3;                 // 8 lanes (32 floats) per head
    float a = ex[(size_t)eid * HEADS + head] /
              (s[dst * HEADS + head] + 1e-16f);
    float4 hv = *(const float4*)&h[(size_t)src * FDIM + lane * 4];
    float* outp = &out[(size_t)dst * FDIM + lane * 4];
    asm volatile("red.global.add.v4.f32 [%0], {%1,%2,%3,%4};"
                 :: "l"(outp), "f"(hv.x * a), "f"(hv.y * a),
                    "f"(hv.z * a), "f"(hv.w * a)
                 : "memory");
}

// ---------------- MLP head: sigmoid(relu([x3,x0]@W1+b1)@W2+b2), warp per node ----------------
__global__ void mlp_kernel(const float* __restrict__ x3,
                           const float* __restrict__ x0,
                           const float* __restrict__ W1,
                           const float* __restrict__ b1,
                           const float* __restrict__ W2,
                           const float* __restrict__ b2,
                           float* __restrict__ out, int N) {
    __shared__ float W1s[256 * 32];
    __shared__ float W2s[32];
    __shared__ float b1s[32];
    int tid = threadIdx.x;
    for (int i = tid; i < 256 * 32; i += blockDim.x) W1s[i] = W1[i];
    if (tid < 32) { W2s[tid] = W2[tid]; b1s[tid] = b1[tid]; }
    __syncthreads();
    int warp = tid >> 5, lane = tid & 31;
    int node = blockIdx.x * (blockDim.x >> 5) + warp;
    if (node >= N) return;
    float acc = 0.f;
    #pragma unroll
    for (int blk = 0; blk < 8; blk++) {
        const float* xp = (blk < 4) ? &x3[(size_t)node * FDIM + blk * 32]
                                    : &x0[(size_t)node * FDIM + (blk - 4) * 32];
        float xv = xp[lane];
        #pragma unroll
        for (int i = 0; i < 32; i++) {
            float v = __shfl_sync(0xffffffffu, xv, i);
            acc += v * W1s[(blk * 32 + i) * 32 + lane];
        }
    }
    float hv = fmaxf(acc + b1s[lane], 0.f);
    float p = hv * W2s[lane];
    #pragma unroll
    for (int off = 16; off; off >>= 1)
        p += __shfl_down_sync(0xffffffffu, p, off);
    if (lane == 0)
        out[node] = 1.f / (1.f + __expf(-(p + b2[0])));
}

// ---------------- host launcher ----------------
extern "C" void kernel_launch(void* const* d_in, const int* in_sizes, int n_in,
                              void* d_out, int out_size) {
    const float* x       = (const float*)d_in[0];
    const int*   ei      = (const int*)  d_in[1];
    const float* W       = (const float*)d_in[2];
    const float* att_src = (const float*)d_in[3];
    const float* att_dst = (const float*)d_in[4];
    const float* b_conv  = (const float*)d_in[5];
    const float* W1      = (const float*)d_in[6];
    const float* b1      = (const float*)d_in[7];
    const float* W2      = (const float*)d_in[8];
    const float* b2      = (const float*)d_in[9];

    int N  = in_sizes[0] / FDIM;
    int E  = in_sizes[1] / 2;
    int L  = in_sizes[2] / (FDIM * FDIM);
    int EP = E + N;

    float *hb, *xa, *xb, *eb, *asb, *adb, *sb; unsigned* mb;
    cudaGetSymbolAddress((void**)&hb,  g_h);
    cudaGetSymbolAddress((void**)&xa,  g_xa);
    cudaGetSymbolAddress((void**)&xb,  g_xb);
    cudaGetSymbolAddress((void**)&eb,  g_e);
    cudaGetSymbolAddress((void**)&asb, g_as);
    cudaGetSymbolAddress((void**)&adb, g_ad);
    cudaGetSymbolAddress((void**)&mb,  g_m);
    cudaGetSymbolAddress((void**)&sb,  g_s);

    const float* xin = x;
    float* bufs[2] = {xa, xb};

    int gemm_grid = (N + BM - 1) / BM;
    int eb_grid   = (EP + 255) / 256;
    int ag_grid   = (int)(((size_t)EP * 32 + 255) / 256);

    for (int l = 0; l < L; l++) {
        float* outb = bufs[l & 1];
        gemm_kernel<<<gemm_grid, 256>>>(xin, W + (size_t)l * FDIM * FDIM, hb, N);
        prep_kernel<<<N, FDIM>>>(hb, att_src + l * HEADS * CH, att_dst + l * HEADS * CH,
                                 b_conv + l * FDIM, outb, asb, adb, mb, sb, N);
        edge_max_kernel<<<eb_grid, 256>>>(ei, asb, adb, eb, mb, E, EP);
        edge_sum_kernel<<<eb_grid, 256>>>(ei, eb, mb, sb, E, EP);
        edge_aggr_kernel<<<ag_grid, 256>>>(ei, eb, sb, hb, outb, E, EP);
        xin = outb;
    }
    mlp_kernel<<<(N + 7) / 8, 256>>>(xin, x, W1, b1, W2, b2, (float*)d_out, N);
}

// round 2
// speedup vs baseline: 1.4797x; 1.4797x over previous
#include <cuda_runtime.h>
#include <math.h>

#define FDIM 128
#define HEADS 4
#define CH 32
#define NMAX 50000
#define EMAX 1600000
#define EPMAX (EMAX + NMAX)

// ---- static device scratch (allocation-free) ----
__device__ float g_h [NMAX * FDIM];
__device__ float g_xa[NMAX * FDIM];
__device__ float g_xb[NMAX * FDIM];
__device__ float g_as[NMAX * HEADS];
__device__ float g_ad[NMAX * HEADS];
__device__ int   g_cnt [NMAX];
__device__ int   g_rptr[NMAX];
__device__ int   g_fill[NMAX];
__device__ int   g_bsum[64];
__device__ int   g_csrc[EPMAX];

// =============== CSR build (counting sort by dst) ===============
__global__ void zero_cnt_kernel(int* __restrict__ cnt, int N) {
    int i = blockIdx.x * blockDim.x + threadIdx.x;
    if (i < N) cnt[i] = 0;
}

__global__ void hist_kernel(const int* __restrict__ ei, int* __restrict__ cnt,
                            int E, int EP) {
    int e = blockIdx.x * blockDim.x + threadIdx.x;
    if (e >= EP) return;
    int dst = (e < E) ? ei[E + e] : (e - E);
    atomicAdd(&cnt[dst], 1);
}

// block-local exclusive scan: 1024 items / block (256 thr x 4)
__global__ void scan1_kernel(const int* __restrict__ cnt, int* __restrict__ rptr,
                             int* __restrict__ bsum, int N) {
    __shared__ int sh[256];
    int t = threadIdx.x;
    int base = blockIdx.x * 1024;
    int v[4]; int s = 0;
    #pragma unroll
    for (int j = 0; j < 4; j++) {
        int idx = base + t * 4 + j;
        v[j] = (idx < N) ? cnt[idx] : 0;
        s += v[j];
    }
    sh[t] = s; __syncthreads();
    #pragma unroll
    for (int off = 1; off < 256; off <<= 1) {
        int x = (t >= off) ? sh[t - off] : 0;
        __syncthreads();
        sh[t] += x;
        __syncthreads();
    }
    int run = (t ? sh[t - 1] : 0);
    #pragma unroll
    for (int j = 0; j < 4; j++) {
        int idx = base + t * 4 + j;
        if (idx < N) rptr[idx] = run;
        run += v[j];
    }
    if (t == 255) bsum[blockIdx.x] = sh[255];
}

__global__ void scan2_kernel(int* __restrict__ rptr, int* __restrict__ fill,
                             const int* __restrict__ bsum, int N) {
    __shared__ int off;
    if (threadIdx.x == 0) {
        int s = 0;
        for (int i = 0; i < blockIdx.x; i++) s += bsum[i];
        off = s;
    }
    __syncthreads();
    int base = blockIdx.x * 1024;
    #pragma unroll
    for (int j = 0; j < 4; j++) {
        int idx = base + threadIdx.x * 4 + j;
        if (idx < N) {
            int r = rptr[idx] + off;
            rptr[idx] = r;
            fill[idx] = r;
        }
    }
}

__global__ void scatter_kernel(const int* __restrict__ ei, int* __restrict__ fill,
                               int* __restrict__ csrc, int E, int EP) {
    int e = blockIdx.x * blockDim.x + threadIdx.x;
    if (e >= EP) return;
    int src, dst;
    if (e < E) { src = ei[e]; dst = ei[E + e]; }
    else       { src = dst = e - E; }
    int pos = atomicAdd(&fill[dst], 1);
    csrc[pos] = src;
}

// =============== GEMM: C[N,128] = A[N,128] @ B[128,128] ===============
// 128x128 block tile, BK=16, 256 threads, 8x8 microtile
__global__ void gemm_kernel(const float* __restrict__ A,
                            const float* __restrict__ B,
                            float* __restrict__ C, int N) {
    __shared__ float As[16][132];   // transposed, padded
    __shared__ float Bs[16][128];
    int tid = threadIdx.x;
    int tx = tid & 15;        // 0..15 col group
    int ty = tid >> 4;        // 0..15 row group
    int rowBlock = blockIdx.x * 128;

    float acc[8][8];
    #pragma unroll
    for (int i = 0; i < 8; i++)
        #pragma unroll
        for (int j = 0; j < 8; j++) acc[i][j] = 0.f;

    for (int k0 = 0; k0 < FDIM; k0 += 16) {
        // load A tile (128 rows x 16 cols) transposed into As
        #pragma unroll
        for (int q = 0; q < 2; q++) {
            int idx = tid * 2 + q;         // 0..511 float4 ids
            int row = idx >> 2;            // 0..127
            int c4  = idx & 3;             // 0..3
            int gr = rowBlock + row;
            float4 av = make_float4(0.f, 0.f, 0.f, 0.f);
            if (gr < N) av = *(const float4*)&A[(size_t)gr * FDIM + k0 + c4 * 4];
            As[c4 * 4 + 0][row] = av.x;
            As[c4 * 4 + 1][row] = av.y;
            As[c4 * 4 + 2][row] = av.z;
            As[c4 * 4 + 3][row] = av.w;
        }
        // load B tile (16 rows x 128 cols)
        #pragma unroll
        for (int q = 0; q < 2; q++) {
            int idx = tid * 2 + q;
            int row = idx >> 5;            // 0..15
            int c4  = idx & 31;            // 0..31
            *(float4*)&Bs[row][c4 * 4] =
                *(const float4*)&B[(size_t)(k0 + row) * FDIM + c4 * 4];
        }
        __syncthreads();
        #pragma unroll
        for (int kk = 0; kk < 16; kk++) {
            float af[8], bf[8];
            *(float4*)&af[0] = *(float4*)&As[kk][ty * 8];
            *(float4*)&af[4] = *(float4*)&As[kk][ty * 8 + 4];
            *(float4*)&bf[0] = *(float4*)&Bs[kk][tx * 8];
            *(float4*)&bf[4] = *(float4*)&Bs[kk][tx * 8 + 4];
            #pragma unroll
            for (int i = 0; i < 8; i++)
                #pragma unroll
                for (int j = 0; j < 8; j++)
                    acc[i][j] += af[i] * bf[j];
        }
        __syncthreads();
    }
    #pragma unroll
    for (int i = 0; i < 8; i++) {
        int gr = rowBlock + ty * 8 + i;
        if (gr < N) {
            *(float4*)&C[(size_t)gr * FDIM + tx * 8]     = *(float4*)&acc[i][0];
            *(float4*)&C[(size_t)gr * FDIM + tx * 8 + 4] = *(float4*)&acc[i][4];
        }
    }
}

// =============== per-node alpha_src / alpha_dst ===============
__global__ void prep_kernel(const float* __restrict__ h,
                            const float* __restrict__ att_s,
                            const float* __restrict__ att_d,
                            float* __restrict__ as_, float* __restrict__ ad_,
                            int N) {
    int n = blockIdx.x;
    if (n >= N) return;
    int c = threadIdx.x;              // 0..127
    int head = c >> 5, lane = c & 31;
    float hv = h[(size_t)n * FDIM + c];
    float vs = hv * att_s[head * CH + lane];
    float vd = hv * att_d[head * CH + lane];
    #pragma unroll
    for (int off = 16; off; off >>= 1) {
        vs += __shfl_down_sync(0xffffffffu, vs, off);
        vd += __shfl_down_sync(0xffffffffu, vd, off);
    }
    if (lane == 0) {
        as_[n * HEADS + head] = vs;
        ad_[n * HEADS + head] = vd;
    }
}

// =============== fused softmax + aggregation: warp per dst node ===============
// out[dst] = (sum_e exp(leaky(as[src]+ad[dst])) * h[src]) / (sum_e exp(...)) + bias
// (no max-subtraction: e values are O(1), exp cannot overflow fp32)
__global__ void aggr_kernel(const int* __restrict__ csrc,
                            const int* __restrict__ rptr,
                            const int* __restrict__ cnt,
                            const float* __restrict__ as_,
                            const float* __restrict__ ad_,
                            const float* __restrict__ h,
                            const float* __restrict__ bias,
                            float* __restrict__ out, int N) {
    int gtid = blockIdx.x * blockDim.x + threadIdx.x;
    int dst = gtid >> 5;
    int lane = gtid & 31;
    if (dst >= N) return;
    int beg = rptr[dst];
    int deg = cnt[dst];
    int hd = lane >> 3;                       // head for channels lane*4..+3
    float adv = ad_[dst * HEADS + hd];
    float acc0 = 0.f, acc1 = 0.f, acc2 = 0.f, acc3 = 0.f;
    float ssum = 0.f;
    for (int i0 = 0; i0 < deg; i0 += 32) {
        int mySrc = (i0 + lane < deg) ? csrc[beg + i0 + lane] : 0;
        int m = min(32, deg - i0);
        for (int j = 0; j < m; j++) {
            int src = __shfl_sync(0xffffffffu, mySrc, j);
            float e = as_[src * HEADS + hd] + adv;
            e = (e > 0.f) ? e : 0.2f * e;
            float ex = __expf(e);
            ssum += ex;
            float4 hv = *(const float4*)&h[(size_t)src * FDIM + lane * 4];
            acc0 += hv.x * ex;
            acc1 += hv.y * ex;
            acc2 += hv.z * ex;
            acc3 += hv.w * ex;
        }
    }
    float inv = 1.f / (ssum + 1e-16f);
    float4 b4 = *(const float4*)&bias[lane * 4];
    float4 o = make_float4(acc0 * inv + b4.x, acc1 * inv + b4.y,
                           acc2 * inv + b4.z, acc3 * inv + b4.w);
    *(float4*)&out[(size_t)dst * FDIM + lane * 4] = o;
}

// =============== MLP head: sigmoid(relu([x3,x0]@W1+b1)@W2+b2) ===============
__global__ void mlp_kernel(const float* __restrict__ x3,
                           const float* __restrict__ x0,
                           const float* __restrict__ W1,
                           const float* __restrict__ b1,
                           const float* __restrict__ W2,
                           const float* __restrict__ b2,
                           float* __restrict__ out, int N) {
    __shared__ float W1s[256 * 32];
    __shared__ float W2s[32];
    __shared__ float b1s[32];
    int tid = threadIdx.x;
    for (int i = tid; i < 256 * 32; i += blockDim.x) W1s[i] = W1[i];
    if (tid < 32) { W2s[tid] = W2[tid]; b1s[tid] = b1[tid]; }
    __syncthreads();
    int warp = tid >> 5, lane = tid & 31;
    int node = blockIdx.x * (blockDim.x >> 5) + warp;
    if (node >= N) return;
    float acc = 0.f;
    #pragma unroll
    for (int blk = 0; blk < 8; blk++) {
        const float* xp = (blk < 4) ? &x3[(size_t)node * FDIM + blk * 32]
                                    : &x0[(size_t)node * FDIM + (blk - 4) * 32];
        float xv = xp[lane];
        #pragma unroll
        for (int i = 0; i < 32; i++) {
            float v = __shfl_sync(0xffffffffu, xv, i);
            acc += v * W1s[(blk * 32 + i) * 32 + lane];
        }
    }
    float hv = fmaxf(acc + b1s[lane], 0.f);
    float p = hv * W2s[lane];
    #pragma unroll
    for (int off = 16; off; off >>= 1)
        p += __shfl_down_sync(0xffffffffu, p, off);
    if (lane == 0)
        out[node] = 1.f / (1.f + __expf(-(p + b2[0])));
}

// =============== host launcher ===============
extern "C" void kernel_launch(void* const* d_in, const int* in_sizes, int n_in,
                              void* d_out, int out_size) {
    const float* x       = (const float*)d_in[0];
    const int*   ei      = (const int*)  d_in[1];
    const float* W       = (const float*)d_in[2];
    const float* att_src = (const float*)d_in[3];
    const float* att_dst = (const float*)d_in[4];
    const float* b_conv  = (const float*)d_in[5];
    const float* W1      = (const float*)d_in[6];
    const float* b1      = (const float*)d_in[7];
    const float* W2      = (const float*)d_in[8];
    const float* b2      = (const float*)d_in[9];

    int N  = in_sizes[0] / FDIM;
    int E  = in_sizes[1] / 2;
    int L  = in_sizes[2] / (FDIM * FDIM);
    int EP = E + N;

    float *hb, *xa, *xb, *asb, *adb;
    int *cnt, *rptr, *fill, *bsum, *csrc;
    cudaGetSymbolAddress((void**)&hb,   g_h);
    cudaGetSymbolAddress((void**)&xa,   g_xa);
    cudaGetSymbolAddress((void**)&xb,   g_xb);
    cudaGetSymbolAddress((void**)&asb,  g_as);
    cudaGetSymbolAddress((void**)&adb,  g_ad);
    cudaGetSymbolAddress((void**)&cnt,  g_cnt);
    cudaGetSymbolAddress((void**)&rptr, g_rptr);
    cudaGetSymbolAddress((void**)&fill, g_fill);
    cudaGetSymbolAddress((void**)&bsum, g_bsum);
    cudaGetSymbolAddress((void**)&csrc, g_csrc);

    // ---- CSR build (dst-sorted adjacency, incl. self loops) ----
    int nb_scan = (N + 1023) / 1024;
    zero_cnt_kernel<<<(N + 255) / 256, 256>>>(cnt, N);
    hist_kernel<<<(EP + 255) / 256, 256>>>(ei, cnt, E, EP);
    scan1_kernel<<<nb_scan, 256>>>(cnt, rptr, bsum, N);
    scan2_kernel<<<nb_scan, 256>>>(rptr, fill, bsum, N);
    scatter_kernel<<<(EP + 255) / 256, 256>>>(ei, fill, csrc, E, EP);

    // ---- layers ----
    const float* xin = x;
    float* bufs[2] = {xa, xb};
    int gemm_grid = (N + 127) / 128;
    int aggr_grid = (int)(((size_t)N * 32 + 255) / 256);

    for (int l = 0; l < L; l++) {
        float* outb = bufs[l & 1];
        gemm_kernel<<<gemm_grid, 256>>>(xin, W + (size_t)l * FDIM * FDIM, hb, N);
        prep_kernel<<<N, FDIM>>>(hb, att_src + l * HEADS * CH,
                                 att_dst + l * HEADS * CH, asb, adb, N);
        aggr_kernel<<<aggr_grid, 256>>>(csrc, rptr, cnt, asb, adb, hb,
                                        b_conv + l * FDIM, outb, N);
        xin = outb;
    }
    mlp_kernel<<<(N + 7) / 8, 256>>>(xin, x, W1, b1, W2, b2, (float*)d_out, N);
}

// round 3
// speedup vs baseline: 2.3317x; 1.5758x over previous
#include <cuda_runtime.h>
#include <math.h>

#define FDIM 128
#define HEADS 4
#define CH 32
#define NMAX 50000
#define EMAX 1600000
#define EPMAX (EMAX + NMAX)

// ---- static device scratch (allocation-free) ----
__device__ float g_h [NMAX * FDIM];
__device__ float g_xa[NMAX * FDIM];
__device__ float g_xb[NMAX * FDIM];
__device__ float g_as[NMAX * HEADS];
__device__ float g_ad[NMAX * HEADS];
__device__ int   g_cnt [NMAX];
__device__ int   g_rptr[NMAX];
__device__ int   g_fill[NMAX];
__device__ int   g_bsum[64];
__device__ int   g_boff[64];
__device__ int   g_csrc[EPMAX];

// =============== CSR build (counting sort by dst) ===============
__global__ void zero_cnt_kernel(int* __restrict__ cnt, int N) {
    int i = blockIdx.x * blockDim.x + threadIdx.x;
    if (i < N) cnt[i] = 0;
}

__global__ void hist_kernel(const int* __restrict__ ei, int* __restrict__ cnt,
                            int E, int EP) {
    int e = blockIdx.x * blockDim.x + threadIdx.x;
    if (e >= EP) return;
    int dst = (e < E) ? ei[E + e] : (e - E);
    atomicAdd(&cnt[dst], 1);
}

__global__ void scan1_kernel(const int* __restrict__ cnt, int* __restrict__ rptr,
                             int* __restrict__ bsum, int N) {
    __shared__ int sh[256];
    int t = threadIdx.x;
    int base = blockIdx.x * 1024;
    int v[4]; int s = 0;
    #pragma unroll
    for (int j = 0; j < 4; j++) {
        int idx = base + t * 4 + j;
        v[j] = (idx < N) ? cnt[idx] : 0;
        s += v[j];
    }
    sh[t] = s; __syncthreads();
    #pragma unroll
    for (int off = 1; off < 256; off <<= 1) {
        int x = (t >= off) ? sh[t - off] : 0;
        __syncthreads();
        sh[t] += x;
        __syncthreads();
    }
    int run = (t ? sh[t - 1] : 0);
    #pragma unroll
    for (int j = 0; j < 4; j++) {
        int idx = base + t * 4 + j;
        if (idx < N) rptr[idx] = run;
        run += v[j];
    }
    if (t == 255) bsum[blockIdx.x] = sh[255];
}

// exclusive scan of up to 64 block sums, one block of 64 threads
__global__ void scan_bsum_kernel(const int* __restrict__ bsum,
                                 int* __restrict__ boff, int nb) {
    __shared__ int sh[64];
    int t = threadIdx.x;
    sh[t] = (t < nb) ? bsum[t] : 0;
    __syncthreads();
    #pragma unroll
    for (int off = 1; off < 64; off <<= 1) {
        int x = (t >= off) ? sh[t - off] : 0;
        __syncthreads();
        sh[t] += x;
        __syncthreads();
    }
    if (t < nb) boff[t] = (t ? sh[t - 1] : 0);
}

__global__ void scan2_kernel(int* __restrict__ rptr, int* __restrict__ fill,
                             const int* __restrict__ boff, int N) {
    int off = boff[blockIdx.x];
    int base = blockIdx.x * 1024;
    #pragma unroll
    for (int j = 0; j < 4; j++) {
        int idx = base + threadIdx.x * 4 + j;
        if (idx < N) {
            int r = rptr[idx] + off;
            rptr[idx] = r;
            fill[idx] = r;
        }
    }
}

__global__ void scatter_kernel(const int* __restrict__ ei, int* __restrict__ fill,
                               int* __restrict__ csrc, int E, int EP) {
    int e = blockIdx.x * blockDim.x + threadIdx.x;
    if (e >= EP) return;
    int src, dst;
    if (e < E) { src = ei[e]; dst = ei[E + e]; }
    else       { src = dst = e - E; }
    int pos = atomicAdd(&fill[dst], 1);
    csrc[pos] = src;
}

// =============== GEMM: C[N,128] = A[N,128] @ B[128,128] ===============
// One-shot staging: full 128x128 A block (transposed) + full B in smem.
// 256 threads, 8x8 microtile, single __syncthreads.
#define GEMM_SMEM_BYTES ((128 * 132 + 128 * 128) * 4)
__global__ void gemm_kernel(const float* __restrict__ A,
                            const float* __restrict__ B,
                            float* __restrict__ C, int N) {
    extern __shared__ float smem[];
    float (*As)[132] = (float(*)[132])smem;               // [k][row]
    float (*Bs)[128] = (float(*)[128])(smem + 128 * 132); // [k][col]
    int tid = threadIdx.x;
    int tx = tid & 15;
    int ty = tid >> 4;
    int rowBlock = blockIdx.x * 128;

    // stage A (transposed) and B: 16 float4 each per thread, coalesced
    #pragma unroll
    for (int i = 0; i < 16; i++) {
        int idx = i * 256 + tid;        // 0..4095 float4 ids
        int row = idx >> 5;             // 0..127
        int c4  = idx & 31;             // 0..31
        int gr = rowBlock + row;
        float4 av = make_float4(0.f, 0.f, 0.f, 0.f);
        if (gr < N) av = *(const float4*)&A[(size_t)gr * FDIM + c4 * 4];
        As[c4 * 4 + 0][row] = av.x;
        As[c4 * 4 + 1][row] = av.y;
        As[c4 * 4 + 2][row] = av.z;
        As[c4 * 4 + 3][row] = av.w;
        *(float4*)&Bs[row][c4 * 4] = *(const float4*)&B[(size_t)row * FDIM + c4 * 4];
    }
    __syncthreads();

    float acc[8][8];
    #pragma unroll
    for (int i = 0; i < 8; i++)
        #pragma unroll
        for (int j = 0; j < 8; j++) acc[i][j] = 0.f;

    #pragma unroll 8
    for (int kk = 0; kk < 128; kk++) {
        float af[8], bf[8];
        *(float4*)&af[0] = *(float4*)&As[kk][ty * 8];
        *(float4*)&af[4] = *(float4*)&As[kk][ty * 8 + 4];
        *(float4*)&bf[0] = *(float4*)&Bs[kk][tx * 8];
        *(float4*)&bf[4] = *(float4*)&Bs[kk][tx * 8 + 4];
        #pragma unroll
        for (int i = 0; i < 8; i++)
            #pragma unroll
            for (int j = 0; j < 8; j++)
                acc[i][j] += af[i] * bf[j];
    }

    #pragma unroll
    for (int i = 0; i < 8; i++) {
        int gr = rowBlock + ty * 8 + i;
        if (gr < N) {
            *(float4*)&C[(size_t)gr * FDIM + tx * 8]     = *(float4*)&acc[i][0];
            *(float4*)&C[(size_t)gr * FDIM + tx * 8 + 4] = *(float4*)&acc[i][4];
        }
    }
}

// =============== per-node alpha_src / alpha_dst ===============
__global__ void prep_kernel(const float* __restrict__ h,
                            const float* __restrict__ att_s,
                            const float* __restrict__ att_d,
                            float* __restrict__ as_, float* __restrict__ ad_,
                            int N) {
    int n = blockIdx.x * 2 + (threadIdx.x >> 7);
    if (n >= N) return;
    int c = threadIdx.x & 127;
    int head = c >> 5, lane = c & 31;
    float hv = h[(size_t)n * FDIM + c];
    float vs = hv * att_s[head * CH + lane];
    float vd = hv * att_d[head * CH + lane];
    #pragma unroll
    for (int off = 16; off; off >>= 1) {
        vs += __shfl_down_sync(0xffffffffu, vs, off);
        vd += __shfl_down_sync(0xffffffffu, vd, off);
    }
    if (lane == 0) {
        as_[n * HEADS + head] = vs;
        ad_[n * HEADS + head] = vd;
    }
}

// =============== fused softmax + aggregation: warp per dst, 8-edge batches ===============
__global__ void aggr_kernel(const int* __restrict__ csrc,
                            const int* __restrict__ rptr,
                            const int* __restrict__ cnt,
                            const float* __restrict__ as_,
                            const float* __restrict__ ad_,
                            const float* __restrict__ h,
                            const float* __restrict__ bias,
                            float* __restrict__ out, int N) {
    int gtid = blockIdx.x * blockDim.x + threadIdx.x;
    int dst = gtid >> 5;
    int lane = gtid & 31;
    if (dst >= N) return;
    int beg = rptr[dst];
    int deg = cnt[dst];
    int hd = lane >> 3;
    float adv = ad_[dst * HEADS + hd];
    float acc0 = 0.f, acc1 = 0.f, acc2 = 0.f, acc3 = 0.f;
    float ssum = 0.f;

    for (int i0 = 0; i0 < deg; i0 += 32) {
        int li = i0 + lane;
        int mySrc = csrc[beg + ((li < deg) ? li : (deg - 1))];
        int m = min(32, deg - i0);
        int j = 0;
        for (; j + 8 <= m; j += 8) {
            int s[8]; float asv[8]; float4 hv[8];
            #pragma unroll
            for (int q = 0; q < 8; q++)
                s[q] = __shfl_sync(0xffffffffu, mySrc, j + q);
            #pragma unroll
            for (int q = 0; q < 8; q++)
                asv[q] = as_[s[q] * HEADS + hd];
            #pragma unroll
            for (int q = 0; q < 8; q++)
                hv[q] = *(const float4*)&h[(size_t)s[q] * FDIM + lane * 4];
            #pragma unroll
            for (int q = 0; q < 8; q++) {
                float e = asv[q] + adv;
                e = (e > 0.f) ? e : 0.2f * e;
                float ex = __expf(e);
                ssum += ex;
                acc0 += hv[q].x * ex;
                acc1 += hv[q].y * ex;
                acc2 += hv[q].z * ex;
                acc3 += hv[q].w * ex;
            }
        }
        for (; j < m; j++) {
            int src = __shfl_sync(0xffffffffu, mySrc, j);
            float e = as_[src * HEADS + hd] + adv;
            e = (e > 0.f) ? e : 0.2f * e;
            float ex = __expf(e);
            ssum += ex;
            float4 hv = *(const float4*)&h[(size_t)src * FDIM + lane * 4];
            acc0 += hv.x * ex;
            acc1 += hv.y * ex;
            acc2 += hv.z * ex;
            acc3 += hv.w * ex;
        }
    }
    float inv = 1.f / (ssum + 1e-16f);
    float4 b4 = *(const float4*)&bias[lane * 4];
    float4 o = make_float4(acc0 * inv + b4.x, acc1 * inv + b4.y,
                           acc2 * inv + b4.z, acc3 * inv + b4.w);
    *(float4*)&out[(size_t)dst * FDIM + lane * 4] = o;
}

// =============== MLP head ===============
__global__ void mlp_kernel(const float* __restrict__ x3,
                           const float* __restrict__ x0,
                           const float* __restrict__ W1,
                           const float* __restrict__ b1,
                           const float* __restrict__ W2,
                           const float* __restrict__ b2,
                           float* __restrict__ out, int N) {
    __shared__ float W1s[256 * 32];
    __shared__ float W2s[32];
    __shared__ float b1s[32];
    int tid = threadIdx.x;
    for (int i = tid; i < 256 * 32; i += blockDim.x) W1s[i] = W1[i];
    if (tid < 32) { W2s[tid] = W2[tid]; b1s[tid] = b1[tid]; }
    __syncthreads();
    int warp = tid >> 5, lane = tid & 31;
    int node = blockIdx.x * (blockDim.x >> 5) + warp;
    if (node >= N) return;
    float acc = 0.f;
    #pragma unroll
    for (int blk = 0; blk < 8; blk++) {
        const float* xp = (blk < 4) ? &x3[(size_t)node * FDIM + blk * 32]
                                    : &x0[(size_t)node * FDIM + (blk - 4) * 32];
        float xv = xp[lane];
        #pragma unroll
        for (int i = 0; i < 32; i++) {
            float v = __shfl_sync(0xffffffffu, xv, i);
            acc += v * W1s[(blk * 32 + i) * 32 + lane];
        }
    }
    float hv = fmaxf(acc + b1s[lane], 0.f);
    float p = hv * W2s[lane];
    #pragma unroll
    for (int off = 16; off; off >>= 1)
        p += __shfl_down_sync(0xffffffffu, p, off);
    if (lane == 0)
        out[node] = 1.f / (1.f + __expf(-(p + b2[0])));
}

// =============== host launcher ===============
extern "C" void kernel_launch(void* const* d_in, const int* in_sizes, int n_in,
                              void* d_out, int out_size) {
    const float* x       = (const float*)d_in[0];
    const int*   ei      = (const int*)  d_in[1];
    const float* W       = (const float*)d_in[2];
    const float* att_src = (const float*)d_in[3];
    const float* att_dst = (const float*)d_in[4];
    const float* b_conv  = (const float*)d_in[5];
    const float* W1      = (const float*)d_in[6];
    const float* b1      = (const float*)d_in[7];
    const float* W2      = (const float*)d_in[8];
    const float* b2      = (const float*)d_in[9];

    int N  = in_sizes[0] / FDIM;
    int E  = in_sizes[1] / 2;
    int L  = in_sizes[2] / (FDIM * FDIM);
    int EP = E + N;

    float *hb, *xa, *xb, *asb, *adb;
    int *cnt, *rptr, *fill, *bsum, *boff, *csrc;
    cudaGetSymbolAddress((void**)&hb,   g_h);
    cudaGetSymbolAddress((void**)&xa,   g_xa);
    cudaGetSymbolAddress((void**)&xb,   g_xb);
    cudaGetSymbolAddress((void**)&asb,  g_as);
    cudaGetSymbolAddress((void**)&adb,  g_ad);
    cudaGetSymbolAddress((void**)&cnt,  g_cnt);
    cudaGetSymbolAddress((void**)&rptr, g_rptr);
    cudaGetSymbolAddress((void**)&fill, g_fill);
    cudaGetSymbolAddress((void**)&bsum, g_bsum);
    cudaGetSymbolAddress((void**)&boff, g_boff);
    cudaGetSymbolAddress((void**)&csrc, g_csrc);

    static bool attr_set = false;
    if (!attr_set) {
        cudaFuncSetAttribute(gemm_kernel,
                             cudaFuncAttributeMaxDynamicSharedMemorySize,
                             GEMM_SMEM_BYTES);
        attr_set = true;
    }

    // ---- CSR build ----
    int nb_scan = (N + 1023) / 1024;
    zero_cnt_kernel<<<(N + 255) / 256, 256>>>(cnt, N);
    hist_kernel<<<(EP + 255) / 256, 256>>>(ei, cnt, E, EP);
    scan1_kernel<<<nb_scan, 256>>>(cnt, rptr, bsum, N);
    scan_bsum_kernel<<<1, 64>>>(bsum, boff, nb_scan);
    scan2_kernel<<<nb_scan, 256>>>(rptr, fill, boff, N);
    scatter_kernel<<<(EP + 255) / 256, 256>>>(ei, fill, csrc, E, EP);

    // ---- layers ----
    const float* xin = x;
    float* bufs[2] = {xa, xb};
    int gemm_grid = (N + 127) / 128;
    int aggr_grid = (int)(((size_t)N * 32 + 255) / 256);

    for (int l = 0; l < L; l++) {
        float* outb = bufs[l & 1];
        gemm_kernel<<<gemm_grid, 256, GEMM_SMEM_BYTES>>>(
            xin, W + (size_t)l * FDIM * FDIM, hb, N);
        prep_kernel<<<(N + 1) / 2, 256>>>(hb, att_src + l * HEADS * CH,
                                          att_dst + l * HEADS * CH, asb, adb, N);
        aggr_kernel<<<aggr_grid, 256>>>(csrc, rptr, cnt, asb, adb, hb,
                                        b_conv + l * FDIM, outb, N);
        xin = outb;
    }
    mlp_kernel<<<(N + 7) / 8, 256>>>(xin, x, W1, b1, W2, b2, (float*)d_out, N);
}

// round 6
// speedup vs baseline: 2.4895x; 1.0677x over previous
#include <cuda_runtime.h>
#include <math.h>

#define FDIM 128
#define HEADS 4
#define CH 32
#define NMAX 50000
#define EMAX 1600000
#define EPMAX (EMAX + NMAX)

// ---- static device scratch (allocation-free) ----
__device__ float g_h [NMAX * FDIM];
__device__ float g_xa[NMAX * FDIM];
__device__ float g_xb[NMAX * FDIM];
__device__ float g_as[NMAX * HEADS];
__device__ float g_ad[NMAX * HEADS];
__device__ int   g_cnt [NMAX];
__device__ int   g_rptr[NMAX];
__device__ int   g_fill[NMAX];
__device__ int   g_bsum[64];
__device__ int   g_boff[64];
__device__ int   g_csrc[EPMAX];

// =============== CSR build (counting sort by dst) ===============
// fused zero + histogram: threads [0,N) zero, threads [0,EP) count
__global__ void zero_cnt_kernel(int* __restrict__ cnt, int N) {
    int i = blockIdx.x * blockDim.x + threadIdx.x;
    if (i < N) cnt[i] = 0;
}

__global__ void hist_kernel(const int* __restrict__ ei, int* __restrict__ cnt,
                            int E, int EP) {
    int e = blockIdx.x * blockDim.x + threadIdx.x;
    if (e >= EP) return;
    int dst = (e < E) ? ei[E + e] : (e - E);
    atomicAdd(&cnt[dst], 1);
}

__global__ void scan1_kernel(const int* __restrict__ cnt, int* __restrict__ rptr,
                             int* __restrict__ bsum, int N) {
    __shared__ int sh[256];
    int t = threadIdx.x;
    int base = blockIdx.x * 1024;
    int v[4]; int s = 0;
    #pragma unroll
    for (int j = 0; j < 4; j++) {
        int idx = base + t * 4 + j;
        v[j] = (idx < N) ? cnt[idx] : 0;
        s += v[j];
    }
    sh[t] = s; __syncthreads();
    #pragma unroll
    for (int off = 1; off < 256; off <<= 1) {
        int x = (t >= off) ? sh[t - off] : 0;
        __syncthreads();
        sh[t] += x;
        __syncthreads();
    }
    int run = (t ? sh[t - 1] : 0);
    #pragma unroll
    for (int j = 0; j < 4; j++) {
        int idx = base + t * 4 + j;
        if (idx < N) rptr[idx] = run;
        run += v[j];
    }
    if (t == 255) bsum[blockIdx.x] = sh[255];
}

__global__ void scan_bsum_kernel(const int* __restrict__ bsum,
                                 int* __restrict__ boff, int nb) {
    __shared__ int sh[64];
    int t = threadIdx.x;
    sh[t] = (t < nb) ? bsum[t] : 0;
    __syncthreads();
    #pragma unroll
    for (int off = 1; off < 64; off <<= 1) {
        int x = (t >= off) ? sh[t - off] : 0;
        __syncthreads();
        sh[t] += x;
        __syncthreads();
    }
    if (t < nb) boff[t] = (t ? sh[t - 1] : 0);
}

__global__ void scan2_kernel(int* __restrict__ rptr, int* __restrict__ fill,
                             const int* __restrict__ boff, int N) {
    int off = boff[blockIdx.x];
    int base = blockIdx.x * 1024;
    #pragma unroll
    for (int j = 0; j < 4; j++) {
        int idx = base + threadIdx.x * 4 + j;
        if (idx < N) {
            int r = rptr[idx] + off;
            rptr[idx] = r;
            fill[idx] = r;
        }
    }
}

__global__ void scatter_kernel(const int* __restrict__ ei, int* __restrict__ fill,
                               int* __restrict__ csrc, int E, int EP) {
    int e = blockIdx.x * blockDim.x + threadIdx.x;
    if (e >= EP) return;
    int src, dst;
    if (e < E) { src = ei[e]; dst = ei[E + e]; }
    else       { src = dst = e - E; }
    int pos = atomicAdd(&fill[dst], 1);
    csrc[pos] = src;
}

// =============== GEMM + fused alpha epilogue (all fp32) ===============
// C[N,128] = A[N,128] @ B[128,128]; also alpha_s/alpha_d per (node, head).
#define GEMM_SMEM_BYTES ((128 * 132 + 128 * 128) * 4)
__global__ void gemm_kernel(const float* __restrict__ A,
                            const float* __restrict__ B,
                            const float* __restrict__ att_s,
                            const float* __restrict__ att_d,
                            float* __restrict__ C,
                            float* __restrict__ as_,
                            float* __restrict__ ad_,
                            int N) {
    extern __shared__ float smem[];
    float (*As)[132] = (float(*)[132])smem;               // [k][row]
    float (*Bs)[128] = (float(*)[128])(smem + 128 * 132); // [k][col]
    int tid = threadIdx.x;
    int tx = tid & 15;                 // col group: cols tx*8 .. tx*8+7
    int ty = tid >> 4;                 // row group: rows ty*8 .. ty*8+7
    int rowBlock = blockIdx.x * 128;

    #pragma unroll
    for (int i = 0; i < 16; i++) {
        int idx = i * 256 + tid;
        int row = idx >> 5;
        int c4  = idx & 31;
        int gr = rowBlock + row;
        float4 av = make_float4(0.f, 0.f, 0.f, 0.f);
        if (gr < N) av = *(const float4*)&A[(size_t)gr * FDIM + c4 * 4];
        As[c4 * 4 + 0][row] = av.x;
        As[c4 * 4 + 1][row] = av.y;
        As[c4 * 4 + 2][row] = av.z;
        As[c4 * 4 + 3][row] = av.w;
        *(float4*)&Bs[row][c4 * 4] = *(const float4*)&B[(size_t)row * FDIM + c4 * 4];
    }
    __syncthreads();

    float acc[8][8];
    #pragma unroll
    for (int i = 0; i < 8; i++)
        #pragma unroll
        for (int j = 0; j < 8; j++) acc[i][j] = 0.f;

    #pragma unroll 8
    for (int kk = 0; kk < 128; kk++) {
        float af[8], bf[8];
        *(float4*)&af[0] = *(float4*)&As[kk][ty * 8];
        *(float4*)&af[4] = *(float4*)&As[kk][ty * 8 + 4];
        *(float4*)&bf[0] = *(float4*)&Bs[kk][tx * 8];
        *(float4*)&bf[4] = *(float4*)&Bs[kk][tx * 8 + 4];
        #pragma unroll
        for (int i = 0; i < 8; i++)
            #pragma unroll
            for (int j = 0; j < 8; j++)
                acc[i][j] += af[i] * bf[j];
    }

    // ---- store fp32 h ----
    #pragma unroll
    for (int i = 0; i < 8; i++) {
        int gr = rowBlock + ty * 8 + i;
        if (gr < N) {
            *(float4*)&C[(size_t)gr * FDIM + tx * 8]     = *(float4*)&acc[i][0];
            *(float4*)&C[(size_t)gr * FDIM + tx * 8 + 4] = *(float4*)&acc[i][4];
        }
    }

    // ---- fused alpha epilogue ----
    float sa[8], da[8];
    #pragma unroll
    for (int j = 0; j < 8; j++) {
        sa[j] = att_s[tx * 8 + j];
        da[j] = att_d[tx * 8 + j];
    }
    int head = tx >> 2;
    #pragma unroll
    for (int i = 0; i < 8; i++) {
        float ps = 0.f, pd = 0.f;
        #pragma unroll
        for (int j = 0; j < 8; j++) {
            ps += acc[i][j] * sa[j];
            pd += acc[i][j] * da[j];
        }
        ps += __shfl_down_sync(0xffffffffu, ps, 2);
        pd += __shfl_down_sync(0xffffffffu, pd, 2);
        ps += __shfl_down_sync(0xffffffffu, ps, 1);
        pd += __shfl_down_sync(0xffffffffu, pd, 1);
        if ((tx & 3) == 0) {
            int gr = rowBlock + ty * 8 + i;
            if (gr < N) {
                as_[gr * HEADS + head] = ps;
                ad_[gr * HEADS + head] = pd;
            }
        }
    }
}

// =============== fused softmax + aggregation: warp per dst, 8-edge batches ===============
__global__ void aggr_kernel(const int* __restrict__ csrc,
                            const int* __restrict__ rptr,
                            const int* __restrict__ cnt,
                            const float* __restrict__ as_,
                            const float* __restrict__ ad_,
                            const float* __restrict__ h,
                            const float* __restrict__ bias,
                            float* __restrict__ out, int N) {
    int gtid = blockIdx.x * blockDim.x + threadIdx.x;
    int dst = gtid >> 5;
    int lane = gtid & 31;
    if (dst >= N) return;
    int beg = rptr[dst];
    int deg = cnt[dst];
    int hd = lane >> 3;
    float adv = ad_[dst * HEADS + hd];
    float acc0 = 0.f, acc1 = 0.f, acc2 = 0.f, acc3 = 0.f;
    float ssum = 0.f;

    for (int i0 = 0; i0 < deg; i0 += 32) {
        int li = i0 + lane;
        int mySrc = csrc[beg + ((li < deg) ? li : (deg - 1))];
        int m = min(32, deg - i0);
        int j = 0;
        for (; j + 8 <= m; j += 8) {
            int s[8]; float asv[8]; float4 hv[8];
            #pragma unroll
            for (int q = 0; q < 8; q++)
                s[q] = __shfl_sync(0xffffffffu, mySrc, j + q);
            #pragma unroll
            for (int q = 0; q < 8; q++)
                asv[q] = as_[s[q] * HEADS + hd];
            #pragma unroll
            for (int q = 0; q < 8; q++)
                hv[q] = *(const float4*)&h[(size_t)s[q] * FDIM + lane * 4];
            #pragma unroll
            for (int q = 0; q < 8; q++) {
                float e = asv[q] + adv;
                e = (e > 0.f) ? e : 0.2f * e;
                float ex = __expf(e);
                ssum += ex;
                acc0 += hv[q].x * ex;
                acc1 += hv[q].y * ex;
                acc2 += hv[q].z * ex;
                acc3 += hv[q].w * ex;
            }
        }
        for (; j < m; j++) {
            int src = __shfl_sync(0xffffffffu, mySrc, j);
            float e = as_[src * HEADS + hd] + adv;
            e = (e > 0.f) ? e : 0.2f * e;
            float ex = __expf(e);
            ssum += ex;
            float4 hv = *(const float4*)&h[(size_t)src * FDIM + lane * 4];
            acc0 += hv.x * ex;
            acc1 += hv.y * ex;
            acc2 += hv.z * ex;
            acc3 += hv.w * ex;
        }
    }
    float inv = 1.f / (ssum + 1e-16f);
    float4 b4 = *(const float4*)&bias[lane * 4];
    float4 o = make_float4(acc0 * inv + b4.x, acc1 * inv + b4.y,
                           acc2 * inv + b4.z, acc3 * inv + b4.w);
    *(float4*)&out[(size_t)dst * FDIM + lane * 4] = o;
}

// =============== MLP head ===============
__global__ void mlp_kernel(const float* __restrict__ x3,
                           const float* __restrict__ x0,
                           const float* __restrict__ W1,
                           const float* __restrict__ b1,
                           const float* __restrict__ W2,
                           const float* __restrict__ b2,
                           float* __restrict__ out, int N) {
    __shared__ float W1s[256 * 32];
    __shared__ float W2s[32];
    __shared__ float b1s[32];
    int tid = threadIdx.x;
    for (int i = tid; i < 256 * 32; i += blockDim.x) W1s[i] = W1[i];
    if (tid < 32) { W2s[tid] = W2[tid]; b1s[tid] = b1[tid]; }
    __syncthreads();
    int warp = tid >> 5, lane = tid & 31;
    int node = blockIdx.x * (blockDim.x >> 5) + warp;
    if (node >= N) return;
    float acc = 0.f;
    #pragma unroll
    for (int blk = 0; blk < 8; blk++) {
        const float* xp = (blk < 4) ? &x3[(size_t)node * FDIM + blk * 32]
                                    : &x0[(size_t)node * FDIM + (blk - 4) * 32];
        float xv = xp[lane];
        #pragma unroll
        for (int i = 0; i < 32; i++) {
            float v = __shfl_sync(0xffffffffu, xv, i);
            acc += v * W1s[(blk * 32 + i) * 32 + lane];
        }
    }
    float hv = fmaxf(acc + b1s[lane], 0.f);
    float p = hv * W2s[lane];
    #pragma unroll
    for (int off = 16; off; off >>= 1)
        p += __shfl_down_sync(0xffffffffu, p, off);
    if (lane == 0)
        out[node] = 1.f / (1.f + __expf(-(p + b2[0])));
}

// =============== host launcher ===============
extern "C" void kernel_launch(void* const* d_in, const int* in_sizes, int n_in,
                              void* d_out, int out_size) {
    const float* x       = (const float*)d_in[0];
    const int*   ei      = (const int*)  d_in[1];
    const float* W       = (const float*)d_in[2];
    const float* att_src = (const float*)d_in[3];
    const float* att_dst = (const float*)d_in[4];
    const float* b_conv  = (const float*)d_in[5];
    const float* W1      = (const float*)d_in[6];
    const float* b1      = (const float*)d_in[7];
    const float* W2      = (const float*)d_in[8];
    const float* b2      = (const float*)d_in[9];

    int N  = in_sizes[0] / FDIM;
    int E  = in_sizes[1] / 2;
    int L  = in_sizes[2] / (FDIM * FDIM);
    int EP = E + N;

    float *hb, *xa, *xb, *asb, *adb;
    int *cnt, *rptr, *fill, *bsum, *boff, *csrc;
    cudaGetSymbolAddress((void**)&hb,   g_h);
    cudaGetSymbolAddress((void**)&xa,   g_xa);
    cudaGetSymbolAddress((void**)&xb,   g_xb);
    cudaGetSymbolAddress((void**)&asb,  g_as);
    cudaGetSymbolAddress((void**)&adb,  g_ad);
    cudaGetSymbolAddress((void**)&cnt,  g_cnt);
    cudaGetSymbolAddress((void**)&rptr, g_rptr);
    cudaGetSymbolAddress((void**)&fill, g_fill);
    cudaGetSymbolAddress((void**)&bsum, g_bsum);
    cudaGetSymbolAddress((void**)&boff, g_boff);
    cudaGetSymbolAddress((void**)&csrc, g_csrc);

    static bool attr_set = false;
    if (!attr_set) {
        cudaFuncSetAttribute(gemm_kernel,
                             cudaFuncAttributeMaxDynamicSharedMemorySize,
                             GEMM_SMEM_BYTES);
        attr_set = true;
    }

    // ---- CSR build ----
    int nb_scan = (N + 1023) / 1024;
    zero_cnt_kernel<<<(N + 255) / 256, 256>>>(cnt, N);
    hist_kernel<<<(EP + 255) / 256, 256>>>(ei, cnt, E, EP);
    scan1_kernel<<<nb_scan, 256>>>(cnt, rptr, bsum, N);
    scan_bsum_kernel<<<1, 64>>>(bsum, boff, nb_scan);
    scan2_kernel<<<nb_scan, 256>>>(rptr, fill, boff, N);
    scatter_kernel<<<(EP + 255) / 256, 256>>>(ei, fill, csrc, E, EP);

    // ---- layers ----
    const float* xin = x;
    float* bufs[2] = {xa, xb};
    int gemm_grid = (N + 127) / 128;
    int aggr_grid = (int)(((size_t)N * 32 + 255) / 256);

    for (int l = 0; l < L; l++) {
        float* outb = bufs[l & 1];
        gemm_kernel<<<gemm_grid, 256, GEMM_SMEM_BYTES>>>(
            xin, W + (size_t)l * FDIM * FDIM,
            att_src + l * HEADS * CH, att_dst + l * HEADS * CH,
            hb, asb, adb, N);
        aggr_kernel<<<aggr_grid, 256>>>(csrc, rptr, cnt, asb, adb, hb,
                                        b_conv + l * FDIM, outb, N);
        xin = outb;
    }
    mlp_kernel<<<(N + 7) / 8, 256>>>(xin, x, W1, b1, W2, b2, (float*)d_out, N);
}

// round 8
// speedup vs baseline: 2.5724x; 1.0333x over previous
#include <cuda_runtime.h>
#include <math.h>

#define FDIM 128
#define HEADS 4
#define CH 32
#define NMAX 50000
#define EMAX 1600000
#define EPMAX (EMAX + NMAX)

// ---- static device scratch (allocation-free) ----
__device__ float g_h [NMAX * FDIM];
__device__ float g_xa[NMAX * FDIM];
__device__ float g_xb[NMAX * FDIM];
__device__ float g_as[NMAX * HEADS];
__device__ float g_ad[NMAX * HEADS];
__device__ int   g_cnt [NMAX];
__device__ int   g_rptr[NMAX];
__device__ int   g_fill[NMAX];
__device__ int   g_bsum[64];
__device__ int   g_boff[64];
__device__ int   g_csrc[EPMAX];

// packed f32x2 helpers (FFMA2 — PTX-only, ptxas never auto-fuses)
__device__ __forceinline__ void ffma2(unsigned long long& d,
                                      unsigned long long a,
                                      unsigned long long b) {
    asm("fma.rn.f32x2 %0, %1, %2, %0;" : "+l"(d) : "l"(a), "l"(b));
}
__device__ __forceinline__ unsigned long long dup2(float x) {
    unsigned long long r;
    asm("mov.b64 %0, {%1, %1};" : "=l"(r) : "f"(x));
    return r;
}

// =============== CSR build (counting sort by dst) ===============
__global__ void zero_cnt_kernel(int* __restrict__ cnt, int N) {
    int i = blockIdx.x * blockDim.x + threadIdx.x;
    if (i < N) cnt[i] = 0;
}

__global__ void hist_kernel(const int* __restrict__ ei, int* __restrict__ cnt,
                            int E, int EP) {
    int e = blockIdx.x * blockDim.x + threadIdx.x;
    if (e >= EP) return;
    int dst = (e < E) ? ei[E + e] : (e - E);
    atomicAdd(&cnt[dst], 1);
}

__global__ void scan1_kernel(const int* __restrict__ cnt, int* __restrict__ rptr,
                             int* __restrict__ bsum, int N) {
    __shared__ int sh[256];
    int t = threadIdx.x;
    int base = blockIdx.x * 1024;
    int v[4]; int s = 0;
    #pragma unroll
    for (int j = 0; j < 4; j++) {
        int idx = base + t * 4 + j;
        v[j] = (idx < N) ? cnt[idx] : 0;
        s += v[j];
    }
    sh[t] = s; __syncthreads();
    #pragma unroll
    for (int off = 1; off < 256; off <<= 1) {
        int x = (t >= off) ? sh[t - off] : 0;
        __syncthreads();
        sh[t] += x;
        __syncthreads();
    }
    int run = (t ? sh[t - 1] : 0);
    #pragma unroll
    for (int j = 0; j < 4; j++) {
        int idx = base + t * 4 + j;
        if (idx < N) rptr[idx] = run;
        run += v[j];
    }
    if (t == 255) bsum[blockIdx.x] = sh[255];
}

__global__ void scan_bsum_kernel(const int* __restrict__ bsum,
                                 int* __restrict__ boff, int nb) {
    __shared__ int sh[64];
    int t = threadIdx.x;
    sh[t] = (t < nb) ? bsum[t] : 0;
    __syncthreads();
    #pragma unroll
    for (int off = 1; off < 64; off <<= 1) {
        int x = (t >= off) ? sh[t - off] : 0;
        __syncthreads();
        sh[t] += x;
        __syncthreads();
    }
    if (t < nb) boff[t] = (t ? sh[t - 1] : 0);
}

__global__ void scan2_kernel(int* __restrict__ rptr, int* __restrict__ fill,
                             const int* __restrict__ boff, int N) {
    int off = boff[blockIdx.x];
    int base = blockIdx.x * 1024;
    #pragma unroll
    for (int j = 0; j < 4; j++) {
        int idx = base + threadIdx.x * 4 + j;
        if (idx < N) {
            int r = rptr[idx] + off;
            rptr[idx] = r;
            fill[idx] = r;
        }
    }
}

__global__ void scatter_kernel(const int* __restrict__ ei, int* __restrict__ fill,
                               int* __restrict__ csrc, int E, int EP) {
    int e = blockIdx.x * blockDim.x + threadIdx.x;
    if (e >= EP) return;
    int src, dst;
    if (e < E) { src = ei[e]; dst = ei[E + e]; }
    else       { src = dst = e - E; }
    int pos = atomicAdd(&fill[dst], 1);
    csrc[pos] = src;
}

// =============== GEMM (FFMA2 mainloop) + fused alpha epilogue ===============
// C[N,128] = A[N,128] @ B[128,128]; accumulators packed as f32x2 over row pairs.
#define GEMM_SMEM_BYTES ((128 * 132 + 128 * 128) * 4)
__global__ void __launch_bounds__(256, 1)
gemm_kernel(const float* __restrict__ A,
            const float* __restrict__ B,
            const float* __restrict__ att_s,
            const float* __restrict__ att_d,
            float* __restrict__ C,
            float* __restrict__ as_,
            float* __restrict__ ad_,
            int N) {
    extern __shared__ float smem[];
    float (*As)[132] = (float(*)[132])smem;               // [k][row]
    float (*Bs)[128] = (float(*)[128])(smem + 128 * 132); // [k][col]
    int tid = threadIdx.x;
    int tx = tid & 15;                 // col group: cols tx*8 .. tx*8+7
    int ty = tid >> 4;                 // row group: rows ty*8 .. ty*8+7
    int rowBlock = blockIdx.x * 128;

    #pragma unroll
    for (int i = 0; i < 16; i++) {
        int idx = i * 256 + tid;
        int row = idx >> 5;
        int c4  = idx & 31;
        int gr = rowBlock + row;
        float4 av = make_float4(0.f, 0.f, 0.f, 0.f);
        if (gr < N) av = *(const float4*)&A[(size_t)gr * FDIM + c4 * 4];
        As[c4 * 4 + 0][row] = av.x;
        As[c4 * 4 + 1][row] = av.y;
        As[c4 * 4 + 2][row] = av.z;
        As[c4 * 4 + 3][row] = av.w;
        *(float4*)&Bs[row][c4 * 4] = *(const float4*)&B[(size_t)row * FDIM + c4 * 4];
    }
    __syncthreads();

    // acc2[ip][j] = packed (acc[2ip][j], acc[2ip+1][j])
    unsigned long long acc2[4][8];
    #pragma unroll
    for (int ip = 0; ip < 4; ip++)
        #pragma unroll
        for (int j = 0; j < 8; j++) acc2[ip][j] = 0ull;

    #pragma unroll 4
    for (int kk = 0; kk < 128; kk++) {
        unsigned long long a2[4];   // consecutive A-row pairs, packed directly
        float bf[8];
        *(float4*)&a2[0] = *(float4*)&As[kk][ty * 8];
        *(float4*)&a2[2] = *(float4*)&As[kk][ty * 8 + 4];
        *(float4*)&bf[0] = *(float4*)&Bs[kk][tx * 8];
        *(float4*)&bf[4] = *(float4*)&Bs[kk][tx * 8 + 4];
        #pragma unroll
        for (int j = 0; j < 8; j++) {
            unsigned long long bd = dup2(bf[j]);
            #pragma unroll
            for (int ip = 0; ip < 4; ip++)
                ffma2(acc2[ip][j], a2[ip], bd);
        }
    }

    // ---- epilogue: store h + fused alpha (extraction = free register halves) ----
    float sa[8], da[8];
    #pragma unroll
    for (int j = 0; j < 8; j++) {
        sa[j] = att_s[tx * 8 + j];
        da[j] = att_d[tx * 8 + j];
    }
    int head = tx >> 2;
    #pragma unroll
    for (int i = 0; i < 8; i++) {
        int ip = i >> 1;
        float r[8];
        #pragma unroll
        for (int j = 0; j < 8; j++) {
            float2 p = *(float2*)&acc2[ip][j];
            r[j] = (i & 1) ? p.y : p.x;
        }
        int gr = rowBlock + ty * 8 + i;
        if (gr < N) {
            *(float4*)&C[(size_t)gr * FDIM + tx * 8]     = *(float4*)&r[0];
            *(float4*)&C[(size_t)gr * FDIM + tx * 8 + 4] = *(float4*)&r[4];
        }
        float ps = 0.f, pd = 0.f;
        #pragma unroll
        for (int j = 0; j < 8; j++) {
            ps += r[j] * sa[j];
            pd += r[j] * da[j];
        }
        ps += __shfl_down_sync(0xffffffffu, ps, 2);
        pd += __shfl_down_sync(0xffffffffu, pd, 2);
        ps += __shfl_down_sync(0xffffffffu, ps, 1);
        pd += __shfl_down_sync(0xffffffffu, pd, 1);
        if ((tx & 3) == 0 && gr < N) {
            as_[gr * HEADS + head] = ps;
            ad_[gr * HEADS + head] = pd;
        }
    }
}

// =============== fused softmax + aggregation: warp per dst, 8-edge batches ===============
__global__ void aggr_kernel(const int* __restrict__ csrc,
                            const int* __restrict__ rptr,
                            const int* __restrict__ cnt,
                            const float* __restrict__ as_,
                            const float* __restrict__ ad_,
                            const float* __restrict__ h,
                            const float* __restrict__ bias,
                            float* __restrict__ out, int N) {
    int gtid = blockIdx.x * blockDim.x + threadIdx.x;
    int dst = gtid >> 5;
    int lane = gtid & 31;
    if (dst >= N) return;
    int beg = rptr[dst];
    int deg = cnt[dst];
    int hd = lane >> 3;
    float adv = ad_[dst * HEADS + hd];
    float acc0 = 0.f, acc1 = 0.f, acc2 = 0.f, acc3 = 0.f;
    float ssum = 0.f;

    for (int i0 = 0; i0 < deg; i0 += 32) {
        int li = i0 + lane;
        int mySrc = csrc[beg + ((li < deg) ? li : (deg - 1))];
        int m = min(32, deg - i0);
        int j = 0;
        for (; j + 8 <= m; j += 8) {
            int s[8]; float asv[8]; float4 hv[8];
            #pragma unroll
            for (int q = 0; q < 8; q++)
                s[q] = __shfl_sync(0xffffffffu, mySrc, j + q);
            #pragma unroll
            for (int q = 0; q < 8; q++)
                asv[q] = as_[s[q] * HEADS + hd];
            #pragma unroll
            for (int q = 0; q < 8; q++)
                hv[q] = *(const float4*)&h[(size_t)s[q] * FDIM + lane * 4];
            #pragma unroll
            for (int q = 0; q < 8; q++) {
                float e = asv[q] + adv;
                e = (e > 0.f) ? e : 0.2f * e;
                float ex = __expf(e);
                ssum += ex;
                acc0 += hv[q].x * ex;
                acc1 += hv[q].y * ex;
                acc2 += hv[q].z * ex;
                acc3 += hv[q].w * ex;
            }
        }
        for (; j < m; j++) {
            int src = __shfl_sync(0xffffffffu, mySrc, j);
            float e = as_[src * HEADS + hd] + adv;
            e = (e > 0.f) ? e : 0.2f * e;
            float ex = __expf(e);
            ssum += ex;
            float4 hv = *(const float4*)&h[(size_t)src * FDIM + lane * 4];
            acc0 += hv.x * ex;
            acc1 += hv.y * ex;
            acc2 += hv.z * ex;
            acc3 += hv.w * ex;
        }
    }
    float inv = 1.f / (ssum + 1e-16f);
    float4 b4 = *(const float4*)&bias[lane * 4];
    float4 o = make_float4(acc0 * inv + b4.x, acc1 * inv + b4.y,
                           acc2 * inv + b4.z, acc3 * inv + b4.w);
    *(float4*)&out[(size_t)dst * FDIM + lane * 4] = o;
}

// =============== MLP head ===============
__global__ void mlp_kernel(const float* __restrict__ x3,
                           const float* __restrict__ x0,
                           const float* __restrict__ W1,
                           const float* __restrict__ b1,
                           const float* __restrict__ W2,
                           const float* __restrict__ b2,
                           float* __restrict__ out, int N) {
    __shared__ float W1s[256 * 32];
    __shared__ float W2s[32];
    __shared__ float b1s[32];
    int tid = threadIdx.x;
    for (int i = tid; i < 256 * 32; i += blockDim.x) W1s[i] = W1[i];
    if (tid < 32) { W2s[tid] = W2[tid]; b1s[tid] = b1[tid]; }
    __syncthreads();
    int warp = tid >> 5, lane = tid & 31;
    int node = blockIdx.x * (blockDim.x >> 5) + warp;
    if (node >= N) return;
    float acc = 0.f;
    #pragma unroll
    for (int blk = 0; blk < 8; blk++) {
        const float* xp = (blk < 4) ? &x3[(size_t)node * FDIM + blk * 32]
                                    : &x0[(size_t)node * FDIM + (blk - 4) * 32];
        float xv = xp[lane];
        #pragma unroll
        for (int i = 0; i < 32; i++) {
            float v = __shfl_sync(0xffffffffu, xv, i);
            acc += v * W1s[(blk * 32 + i) * 32 + lane];
        }
    }
    float hv = fmaxf(acc + b1s[lane], 0.f);
    float p = hv * W2s[lane];
    #pragma unroll
    for (int off = 16; off; off >>= 1)
        p += __shfl_down_sync(0xffffffffu, p, off);
    if (lane == 0)
        out[node] = 1.f / (1.f + __expf(-(p + b2[0])));
}

// =============== host launcher ===============
extern "C" void kernel_launch(void* const* d_in, const int* in_sizes, int n_in,
                              void* d_out, int out_size) {
    const float* x       = (const float*)d_in[0];
    const int*   ei      = (const int*)  d_in[1];
    const float* W       = (const float*)d_in[2];
    const float* att_src = (const float*)d_in[3];
    const float* att_dst = (const float*)d_in[4];
    const float* b_conv  = (const float*)d_in[5];
    const float* W1      = (const float*)d_in[6];
    const float* b1      = (const float*)d_in[7];
    const float* W2      = (const float*)d_in[8];
    const float* b2      = (const float*)d_in[9];

    int N  = in_sizes[0] / FDIM;
    int E  = in_sizes[1] / 2;
    int L  = in_sizes[2] / (FDIM * FDIM);
    int EP = E + N;

    float *hb, *xa, *xb, *asb, *adb;
    int *cnt, *rptr, *fill, *bsum, *boff, *csrc;
    cudaGetSymbolAddress((void**)&hb,   g_h);
    cudaGetSymbolAddress((void**)&xa,   g_xa);
    cudaGetSymbolAddress((void**)&xb,   g_xb);
    cudaGetSymbolAddress((void**)&asb,  g_as);
    cudaGetSymbolAddress((void**)&adb,  g_ad);
    cudaGetSymbolAddress((void**)&cnt,  g_cnt);
    cudaGetSymbolAddress((void**)&rptr, g_rptr);
    cudaGetSymbolAddress((void**)&fill, g_fill);
    cudaGetSymbolAddress((void**)&bsum, g_bsum);
    cudaGetSymbolAddress((void**)&boff, g_boff);
    cudaGetSymbolAddress((void**)&csrc, g_csrc);

    static bool attr_set = false;
    if (!attr_set) {
        cudaFuncSetAttribute(gemm_kernel,
                             cudaFuncAttributeMaxDynamicSharedMemorySize,
                             GEMM_SMEM_BYTES);
        attr_set = true;
    }

    // ---- CSR build ----
    int nb_scan = (N + 1023) / 1024;
    zero_cnt_kernel<<<(N + 255) / 256, 256>>>(cnt, N);
    hist_kernel<<<(EP + 255) / 256, 256>>>(ei, cnt, E, EP);
    scan1_kernel<<<nb_scan, 256>>>(cnt, rptr, bsum, N);
    scan_bsum_kernel<<<1, 64>>>(bsum, boff, nb_scan);
    scan2_kernel<<<nb_scan, 256>>>(rptr, fill, boff, N);
    scatter_kernel<<<(EP + 255) / 256, 256>>>(ei, fill, csrc, E, EP);

    // ---- layers ----
    const float* xin = x;
    float* bufs[2] = {xa, xb};
    int gemm_grid = (N + 127) / 128;
    int aggr_grid = (int)(((size_t)N * 32 + 255) / 256);

    for (int l = 0; l < L; l++) {
        float* outb = bufs[l & 1];
        gemm_kernel<<<gemm_grid, 256, GEMM_SMEM_BYTES>>>(
            xin, W + (size_t)l * FDIM * FDIM,
            att_src + l * HEADS * CH, att_dst + l * HEADS * CH,
            hb, asb, adb, N);
        aggr_kernel<<<aggr_grid, 256>>>(csrc, rptr, cnt, asb, adb, hb,
                                        b_conv + l * FDIM, outb, N);
        xin = outb;
    }
    mlp_kernel<<<(N + 7) / 8, 256>>>(xin, x, W1, b1, W2, b2, (float*)d_out, N);
}